// round 6
// baseline (speedup 1.0000x reference)
#include <cuda_runtime.h>
#include <cuda_bf16.h>
#include <math.h>
#include <stdint.h>

typedef __nv_bfloat16 bf16;

#define BB 1024
#define DD 128
#define WW 512
#define TT 8
#define NELEM (BB*DD)
#define HELEM (BB*WW)
#define MAX_STEPS 48
#define NBLK 128
#define NTHR 256
#define RTOLc 1e-3f
#define ATOLc 1e-6f

#define SROW 144           // smem row stride bytes (72 bf16)
#define ABYTES (64*SROW)   // 9216
#define STG (4*ABYTES)     // 36864 per pipeline stage
#define NSTG 3

#define A21f 0.161f
#define A31f (-0.008480655492356989f)
#define A32f 0.335480655492357f
#define A41f 2.8971530571054935f
#define A42f (-6.359448489975075f)
#define A43f 4.3622954328695815f
#define A51f 5.325864828439257f
#define A52f (-11.748883564062828f)
#define A53f 7.4955393428898365f
#define A54f (-0.09249506636175525f)
#define A61f 5.86145544294642f
#define A62f (-12.92096931784711f)
#define A63f 8.159367898576159f
#define A64f (-0.071584973281401f)
#define A65f (-0.028269050394068383f)
#define Bc1 0.09646076681806523f
#define Bc2 0.01f
#define Bc3 0.4798896504144996f
#define Bc4 1.379008574103742f
#define Bc5 (-3.290069515436081f)
#define Bc6 2.324710524099774f
#define Ec1 (-0.00178001105222577714f)
#define Ec2 (-0.0008164344596567469f)
#define Ec3 0.007880878010261995f
#define Ec4 (-0.1447110071732629f)
#define Ec5 0.5823571654525552f
#define Ec6 (-0.45808210592918697f)
#define Ec7 0.015151515151515152f

// ---------------- device state ----------------
__device__ __align__(16) float g_y[NELEM], g_ynew[NELEM], g_k[7][NELEM];
__device__ __align__(16) bf16 g_Xhi[NELEM], g_Xlo[NELEM];
__device__ __align__(16) bf16 g_H1hi[HELEM], g_H1lo[HELEM];
__device__ __align__(16) bf16 g_H2hi[HELEM], g_H2lo[HELEM];
__device__ __align__(16) bf16 g_W0hi[WW*DD], g_W0lo[WW*DD];
__device__ __align__(16) bf16 g_W1hi[WW*WW], g_W1lo[WW*WW];
__device__ __align__(16) bf16 g_W2hi[DD*WW], g_W2lo[DD*WW];
__device__ double g_errpart[NBLK];
__device__ volatile float g_t, g_dt, g_h, g_tns;
__device__ volatile int g_si, g_sic, g_done, g_accept, g_hit, g_wrow;
__device__ unsigned g_arrive;

__constant__ float c_coef[6][6] = {
  {A21f,0,0,0,0,0},
  {A31f,A32f,0,0,0,0},
  {A41f,A42f,A43f,0,0,0},
  {A51f,A52f,A53f,A54f,0,0},
  {A61f,A62f,A63f,A64f,A65f,0},
  {Bc1,Bc2,Bc3,Bc4,Bc5,Bc6},
};

// ---------------- helpers ----------------
__device__ __forceinline__ uint32_t smem_u32(const void* p) {
  uint32_t a;
  asm("{ .reg .u64 t; cvta.to.shared.u64 t, %1; cvt.u32.u64 %0, t; }" : "=r"(a) : "l"(p));
  return a;
}
__device__ __forceinline__ void cp16(uint32_t dst, const void* src) {
  asm volatile("cp.async.cg.shared.global [%0], [%1], 16;" :: "r"(dst), "l"(src) : "memory");
}
__device__ __forceinline__ void cp_commit() { asm volatile("cp.async.commit_group;" ::: "memory"); }
__device__ __forceinline__ void cp_wait1() { asm volatile("cp.async.wait_group 1;" ::: "memory"); }

__device__ __forceinline__ void ldmx4(uint32_t* r, const char* base, int row0, int k0) {
  int l = threadIdx.x & 31;
  uint32_t a = smem_u32(base + (row0 + (l & 15)) * SROW + (k0 + ((l >> 4) << 3)) * 2);
  asm volatile("ldmatrix.sync.aligned.m8n8.x4.shared.b16 {%0,%1,%2,%3}, [%4];"
    : "=r"(r[0]), "=r"(r[1]), "=r"(r[2]), "=r"(r[3]) : "r"(a));
}
__device__ __forceinline__ void ldmx2(uint32_t* r, const char* base, int row0, int k0) {
  int l = threadIdx.x & 31;
  uint32_t a = smem_u32(base + (row0 + (l & 7)) * SROW + (k0 + (((l >> 3) & 1) << 3)) * 2);
  asm volatile("ldmatrix.sync.aligned.m8n8.x2.shared.b16 {%0,%1}, [%2];"
    : "=r"(r[0]), "=r"(r[1]) : "r"(a));
}
__device__ __forceinline__ void mma16816(float* c, const uint32_t* a, const uint32_t* b) {
  asm volatile(
    "mma.sync.aligned.m16n8k16.row.col.f32.bf16.bf16.f32 "
    "{%0,%1,%2,%3}, {%4,%5,%6,%7}, {%8,%9}, {%0,%1,%2,%3};"
    : "+f"(c[0]), "+f"(c[1]), "+f"(c[2]), "+f"(c[3])
    : "r"(a[0]), "r"(a[1]), "r"(a[2]), "r"(a[3]), "r"(b[0]), "r"(b[1]));
}

// -------- grid barrier --------
__device__ __forceinline__ void gsync() {
  __syncthreads();
  if (threadIdx.x == 0) {
    __threadfence();
    unsigned t = atomicAdd(&g_arrive, 1u) + 1u;
    unsigned target = ((t + NBLK - 1u) / NBLK) * NBLK;
    while (*(volatile unsigned*)&g_arrive < target) {}
    __threadfence();
  }
  __syncthreads();
}

// -------- MUFU-free softplus (abs err ~2e-6) --------
__device__ __forceinline__ float softplus_f(float x) {
  float t = fabsf(x);
  float s = fminf(t * 1.4426950408889634f, 100.f);
  float n = floorf(s);
  float r = n - s;                       // (-1, 0]
  float p = 1.3215487e-6f;
  p = fmaf(p, r, 1.5252734e-5f);
  p = fmaf(p, r, 1.5403530e-4f);
  p = fmaf(p, r, 1.3333558e-3f);
  p = fmaf(p, r, 9.6181291e-3f);
  p = fmaf(p, r, 5.5504109e-2f);
  p = fmaf(p, r, 2.4022651e-1f);
  p = fmaf(p, r, 6.9314718e-1f);
  p = fmaf(p, r, 1.0f);
  float u = p * __uint_as_float((uint32_t)(127 - (int)n) << 23);  // exp(-t)
  float d = 2.f + u;
  float w = fmaf(-0.1635f, u, 0.4915f);
  w = w * fmaf(-d, w, 2.f);
  w = w * fmaf(-d, w, 2.f);
  float v = u * w;
  float v2 = v * v;
  float g = 0.09090909f;
  g = fmaf(g, v2, 0.11111111f);
  g = fmaf(g, v2, 0.14285714f);
  g = fmaf(g, v2, 0.2f);
  g = fmaf(g, v2, 0.33333333f);
  g = fmaf(g, v2, 1.0f);
  return fmaxf(x, 0.f) + 2.f * v * g;
}

__device__ __forceinline__ void split_pack(float x0, float x1, uint32_t& hv, uint32_t& lv) {
  bf16 h0 = __float2bfloat16(x0), h1 = __float2bfloat16(x1);
  bf16 l0 = __float2bfloat16(x0 - __bfloat162float(h0));
  bf16 l1 = __float2bfloat16(x1 - __bfloat162float(h1));
  hv = (uint32_t)__bfloat16_as_ushort(h0) | ((uint32_t)__bfloat16_as_ushort(h1) << 16);
  lv = (uint32_t)__bfloat16_as_ushort(l0) | ((uint32_t)__bfloat16_as_ushort(l1) << 16);
}

// -------- chunk fill: 4 arrays x 64 rows x 64 cols (bf16) via cp.async --------
__device__ __forceinline__ void fill_chunk(char* dst,
    const bf16* __restrict__ Ahi, const bf16* __restrict__ Alo,
    const bf16* __restrict__ Bhi, const bf16* __restrict__ Blo,
    int ldk, int arow0, int brow0, int brows, int koff)
{
  const int tid = threadIdx.x;
  const int t = tid & 63;
  const int part = tid >> 6;
  const bf16* src;
  bool on = true;
  if (part == 0)      src = Ahi + (arow0 + t) * ldk + koff;
  else if (part == 1) src = Alo + (arow0 + t) * ldk + koff;
  else if (part == 2) { src = Bhi + (brow0 + t) * ldk + koff; on = t < brows; }
  else                { src = Blo + (brow0 + t) * ldk + koff; on = t < brows; }
  if (on) {
    uint32_t d = smem_u32(dst + part * ABYTES + t * SROW);
    #pragma unroll
    for (int j = 0; j < 8; ++j) cp16(d + j * 16, src + j * 8);
  }
}

// ---------------- GEMM1/2: C[64,64] = act(A @ B^T + bias) -> bf16 hi/lo ----------------
template<int NCHUNK, bool SP>
__device__ __forceinline__ void gemm_fwd(char* sm,
    const bf16* __restrict__ Ahi, const bf16* __restrict__ Alo,
    const bf16* __restrict__ Bhi, const bf16* __restrict__ Blo,
    int ldk, int bm, int bn, const float* __restrict__ bias,
    bf16* __restrict__ Chi, bf16* __restrict__ Clo, int ldc)
{
  const int tid = threadIdx.x;
  const int wid = tid >> 5, lane = tid & 31;
  const int wm = wid & 3, wn = wid >> 2;
  const int grp = lane >> 2, tig = lane & 3;

  float acc[4][4] = {};

  fill_chunk(sm, Ahi, Alo, Bhi, Blo, ldk, bm, bn, 64, 0);
  cp_commit();
  if (NCHUNK > 1) fill_chunk(sm + STG, Ahi, Alo, Bhi, Blo, ldk, bm, bn, 64, 64);
  cp_commit();

  for (int c = 0; c < NCHUNK; ++c) {
    cp_wait1();
    __syncthreads();
    if (c + 2 < NCHUNK)
      fill_chunk(sm + ((c + 2) % NSTG) * STG, Ahi, Alo, Bhi, Blo, ldk, bm, bn, 64, (c + 2) * 64);
    cp_commit();
    char* st = sm + (c % NSTG) * STG;
    char* sAh = st;
    char* sAl = st + ABYTES;
    char* sBh = st + 2 * ABYTES;
    char* sBl = st + 3 * ABYTES;
    #pragma unroll
    for (int ks = 0; ks < 4; ++ks) {
      uint32_t ah[4], al[4], bh0[4], bh1[4], bl0[4], bl1[4];
      ldmx4(ah, sAh, wm * 16, ks * 16);
      ldmx4(al, sAl, wm * 16, ks * 16);
      ldmx4(bh0, sBh, wn * 32, ks * 16);
      ldmx4(bl0, sBl, wn * 32, ks * 16);
      ldmx4(bh1, sBh, wn * 32 + 16, ks * 16);
      ldmx4(bl1, sBl, wn * 32 + 16, ks * 16);
      uint32_t bt[2], ct[2];
      bt[0] = bh0[0]; bt[1] = bh0[2]; ct[0] = bl0[0]; ct[1] = bl0[2];
      mma16816(acc[0], ah, bt); mma16816(acc[0], ah, ct); mma16816(acc[0], al, bt);
      bt[0] = bh0[1]; bt[1] = bh0[3]; ct[0] = bl0[1]; ct[1] = bl0[3];
      mma16816(acc[1], ah, bt); mma16816(acc[1], ah, ct); mma16816(acc[1], al, bt);
      bt[0] = bh1[0]; bt[1] = bh1[2]; ct[0] = bl1[0]; ct[1] = bl1[2];
      mma16816(acc[2], ah, bt); mma16816(acc[2], ah, ct); mma16816(acc[2], al, bt);
      bt[0] = bh1[1]; bt[1] = bh1[3]; ct[0] = bl1[1]; ct[1] = bl1[3];
      mma16816(acc[3], ah, bt); mma16816(acc[3], ah, ct); mma16816(acc[3], al, bt);
    }
  }

  #pragma unroll
  for (int nt = 0; nt < 4; ++nt) {
    int n = bn + wn * 32 + nt * 8 + tig * 2;
    int m0 = bm + wm * 16 + grp;
    float bv0 = __ldg(bias + n), bv1 = __ldg(bias + n + 1);
    float x0 = acc[nt][0] + bv0, x1 = acc[nt][1] + bv1;
    float x2 = acc[nt][2] + bv0, x3 = acc[nt][3] + bv1;
    if (SP) { x0 = softplus_f(x0); x1 = softplus_f(x1); x2 = softplus_f(x2); x3 = softplus_f(x3); }
    uint32_t hv, lv;
    split_pack(x0, x1, hv, lv);
    __stcg((uint32_t*)(Chi + m0 * ldc + n), hv);
    __stcg((uint32_t*)(Clo + m0 * ldc + n), lv);
    split_pack(x2, x3, hv, lv);
    __stcg((uint32_t*)(Chi + (m0 + 8) * ldc + n), hv);
    __stcg((uint32_t*)(Clo + (m0 + 8) * ldc + n), lv);
  }
}

// ---------------- GEMM3 (stage S): k_S[64,16] tile + fused RK epilogue ----------------
template<int S>
__device__ __forceinline__ void gemm3_stage(char* sm, int bm, int bn,
                                            const float* __restrict__ b2, double* sd)
{
  const int tid = threadIdx.x;
  const int wid = tid >> 5, lane = tid & 31;
  const int wm = wid & 3, wn = wid >> 2;
  const int grp = lane >> 2, tig = lane & 3;

  float acc[4] = {};

  fill_chunk(sm, g_H2hi, g_H2lo, g_W2hi, g_W2lo, WW, bm, bn, 16, 0);
  cp_commit();
  fill_chunk(sm + STG, g_H2hi, g_H2lo, g_W2hi, g_W2lo, WW, bm, bn, 16, 64);
  cp_commit();

  for (int c = 0; c < 8; ++c) {
    cp_wait1();
    __syncthreads();
    if (c + 2 < 8)
      fill_chunk(sm + ((c + 2) % NSTG) * STG, g_H2hi, g_H2lo, g_W2hi, g_W2lo, WW, bm, bn, 16, (c + 2) * 64);
    cp_commit();
    char* st = sm + (c % NSTG) * STG;
    char* sAh = st;
    char* sAl = st + ABYTES;
    char* sBh = st + 2 * ABYTES;
    char* sBl = st + 3 * ABYTES;
    #pragma unroll
    for (int ks = 0; ks < 4; ++ks) {
      uint32_t ah[4], al[4], bh[2], bl[2];
      ldmx4(ah, sAh, wm * 16, ks * 16);
      ldmx4(al, sAl, wm * 16, ks * 16);
      ldmx2(bh, sBh, wn * 8, ks * 16);
      ldmx2(bl, sBl, wn * 8, ks * 16);
      mma16816(acc, ah, bh);
      mma16816(acc, ah, bl);
      mma16816(acc, al, bh);
    }
  }

  // fused epilogue
  const int n0 = bn + wn * 8 + tig * 2;
  const int m0 = bm + wm * 16 + grp;
  const float h = g_h;
  const int i0 = m0 * DD + n0;
  const int i1 = (m0 + 8) * DD + n0;
  float bv0 = __ldg(b2 + n0), bv1 = __ldg(b2 + n0 + 1);
  float2 v0 = {acc[0] + bv0, acc[1] + bv1};
  float2 v1 = {acc[2] + bv0, acc[3] + bv1};
  __stcg((float2*)(g_k[S] + i0), v0);
  __stcg((float2*)(g_k[S] + i1), v1);

  if constexpr (S <= 5) {
    const int idxs[2] = {i0, i1};
    const float2 vs[2] = {v0, v1};
    #pragma unroll
    for (int r = 0; r < 2; ++r) {
      int ix = idxs[r];
      float2 y2 = __ldcg((const float2*)(g_y + ix));
      float cS = c_coef[S][S];
      float ax = cS * vs[r].x, ay = cS * vs[r].y;
      #pragma unroll
      for (int j = 0; j < S; ++j) {
        float cj = c_coef[S][j];
        float2 kj = __ldcg((const float2*)(g_k[j] + ix));
        ax = fmaf(cj, kj.x, ax);
        ay = fmaf(cj, kj.y, ay);
      }
      float Xx = fmaf(h, ax, y2.x);
      float Xy = fmaf(h, ay, y2.y);
      if constexpr (S == 5) {
        float2 yn = {Xx, Xy};
        __stcg((float2*)(g_ynew + ix), yn);
      }
      uint32_t hv, lv;
      split_pack(Xx, Xy, hv, lv);
      __stcg((uint32_t*)(g_Xhi + ix), hv);
      __stcg((uint32_t*)(g_Xlo + ix), lv);
    }
  } else {
    double ss = 0.0;
    const int idxs[2] = {i0, i1};
    const float2 vs[2] = {v0, v1};
    #pragma unroll
    for (int r = 0; r < 2; ++r) {
      int ix = idxs[r];
      float2 k0 = __ldcg((const float2*)(g_k[0] + ix));
      float2 k1 = __ldcg((const float2*)(g_k[1] + ix));
      float2 k2 = __ldcg((const float2*)(g_k[2] + ix));
      float2 k3 = __ldcg((const float2*)(g_k[3] + ix));
      float2 k4 = __ldcg((const float2*)(g_k[4] + ix));
      float2 k5 = __ldcg((const float2*)(g_k[5] + ix));
      float2 y2 = __ldcg((const float2*)(g_y + ix));
      float2 yn = __ldcg((const float2*)(g_ynew + ix));
      #pragma unroll
      for (int cc = 0; cc < 2; ++cc) {
        float kk0 = cc ? k0.y : k0.x, kk1 = cc ? k1.y : k1.x, kk2 = cc ? k2.y : k2.x;
        float kk3 = cc ? k3.y : k3.x, kk4 = cc ? k4.y : k4.x, kk5 = cc ? k5.y : k5.x;
        float kk6 = cc ? vs[r].y : vs[r].x;
        float yv = cc ? y2.y : y2.x, ynv = cc ? yn.y : yn.x;
        float e = Ec1 * kk0;
        e = fmaf(Ec2, kk1, e);
        e = fmaf(Ec3, kk2, e);
        e = fmaf(Ec4, kk3, e);
        e = fmaf(Ec5, kk4, e);
        e = fmaf(Ec6, kk5, e);
        e = fmaf(Ec7, kk6, e);
        float err = h * e;
        float scale = ATOLc + RTOLc * fmaxf(fabsf(yv), fabsf(ynv));
        float rr = err / scale;
        ss += (double)rr * (double)rr;
      }
    }
    sd[tid] = ss;
    __syncthreads();
    #pragma unroll
    for (int s2 = 128; s2 > 0; s2 >>= 1) {
      if (tid < s2) sd[tid] += sd[tid + s2];
      __syncthreads();
    }
    if (tid == 0) ((volatile double*)g_errpart)[blockIdx.x] = sd[0];
  }
}

// ---------------- one RK stage ----------------
template<int S>
__device__ __forceinline__ void do_stage(char* sm, int bid,
    const float* b0, const float* b1, const float* b2, double* sd)
{
  const int bm = (bid >> 3) << 6;
  const int bn = (bid & 7) << 6;
  gemm_fwd<2, true>(sm, g_Xhi, g_Xlo, g_W0hi, g_W0lo, DD, bm, bn, b0, g_H1hi, g_H1lo, WW);
  gsync();
  gemm_fwd<8, true>(sm, g_H1hi, g_H1lo, g_W1hi, g_W1lo, WW, bm, bn, b1, g_H2hi, g_H2lo, WW);
  gsync();
  gemm3_stage<S>(sm, bm, (bid & 7) << 4, b2, sd);
  gsync();
}

__device__ __forceinline__ void update_phase(int gid4, float* __restrict__ out) {
  float4 v;
  if (g_accept) {
    v = __ldcg((const float4*)(g_ynew + gid4));
    __stcg((float4*)(g_y + gid4), v);
    if (g_hit) *(float4*)(out + g_wrow * NELEM + gid4) = v;
  } else {
    v = __ldcg((const float4*)(g_y + gid4));
  }
  uint2 hv, lv;
  split_pack(v.x, v.y, hv.x, lv.x);
  split_pack(v.z, v.w, hv.y, lv.y);
  __stcg((uint2*)(g_Xhi + gid4), hv);
  __stcg((uint2*)(g_Xlo + gid4), lv);
}

// ---------------- persistent solver ----------------
__global__ void __launch_bounds__(NTHR, 1) solve_kernel(
    const float* __restrict__ ts,
    const float* __restrict__ b0, const float* __restrict__ b1,
    const float* __restrict__ b2, float* __restrict__ out)
{
  extern __shared__ __align__(16) char sm[];
  __shared__ double sd[NTHR];

  const int bid = blockIdx.x;
  const int tid = threadIdx.x;
  const int gid4 = (bid * NTHR + tid) * 4;

  for (int step = 0; step < MAX_STEPS; ++step) {
    update_phase(gid4, out);
    if (bid == 0 && tid == 0) {
      int si = g_si;
      int done = (si >= TT) ? 1 : 0;
      int sic = si < (TT - 1) ? si : (TT - 1);
      float tns = __ldg(ts + sic);
      float h = done ? 0.f : fmaxf(fminf(g_dt, tns - g_t), 0.f);
      g_done = done; g_sic = sic; g_tns = tns; g_h = h;
    }
    gsync();

    do_stage<0>(sm, bid, b0, b1, b2, sd);
    do_stage<1>(sm, bid, b0, b1, b2, sd);
    do_stage<2>(sm, bid, b0, b1, b2, sd);
    do_stage<3>(sm, bid, b0, b1, b2, sd);
    do_stage<4>(sm, bid, b0, b1, b2, sd);
    do_stage<5>(sm, bid, b0, b1, b2, sd);
    do_stage<6>(sm, bid, b0, b1, b2, sd);

    if (bid == 0) {
      double v = (tid < NBLK) ? ((volatile double*)g_errpart)[tid] : 0.0;
      sd[tid] = v;
      __syncthreads();
      #pragma unroll
      for (int s2 = 128; s2 > 0; s2 >>= 1) {
        if (tid < s2) sd[tid] += sd[tid + s2];
        __syncthreads();
      }
      if (tid == 0) {
        float enorm = sqrtf((float)(sd[0] / (double)NELEM));
        int done = g_done;
        float h = g_h;
        int accept = (enorm <= 1.0f) && !done;
        float t_new = g_t + h;
        int hit = accept && (t_new >= g_tns - 1e-6f);
        if (accept) g_t = t_new;
        g_accept = accept;
        g_hit = hit;
        g_wrow = g_sic;
        g_si = g_si + hit;
        float factor;
        if (enorm > 0.f) {
          factor = 0.9f * powf(enorm, -0.2f);
          factor = fminf(fmaxf(factor, 0.2f), 10.f);
        } else factor = 10.f;
        if (!done) g_dt = g_dt * factor;
      }
    }
    gsync();
  }
  update_phase(gid4, out);
}

// ---------------- init ----------------
__global__ void init_kernel(const float* __restrict__ ts, const float* __restrict__ y0,
                            const float* __restrict__ W0, const float* __restrict__ W1,
                            const float* __restrict__ W2, float* __restrict__ out)
{
  int idx = blockIdx.x * NTHR + threadIdx.x;
  if (idx < TT * NELEM) out[idx] = (idx < NELEM) ? y0[idx] : 0.f;
  if (idx < NELEM) {
    float v = y0[idx];
    g_y[idx] = v;
    bf16 h = __float2bfloat16(v);
    g_Xhi[idx] = h;
    g_Xlo[idx] = __float2bfloat16(v - __bfloat162float(h));
  }
  if (idx < WW * DD) {
    float w = W0[idx];
    bf16 h = __float2bfloat16(w);
    g_W0hi[idx] = h; g_W0lo[idx] = __float2bfloat16(w - __bfloat162float(h));
    float w2 = W2[idx];
    bf16 h2 = __float2bfloat16(w2);
    g_W2hi[idx] = h2; g_W2lo[idx] = __float2bfloat16(w2 - __bfloat162float(h2));
  }
  if (idx < WW * WW) {
    float w = W1[idx];
    bf16 h = __float2bfloat16(w);
    g_W1hi[idx] = h; g_W1lo[idx] = __float2bfloat16(w - __bfloat162float(h));
  }
  if (idx == 0) {
    g_t = ts[0];
    g_dt = ts[1] - ts[0];
    g_si = 1;
    g_accept = 0;
    g_hit = 0;
    g_wrow = 0;
    g_arrive = 0u;
  }
}

extern "C" void kernel_launch(void* const* d_in, const int* in_sizes, int n_in,
                              void* d_out, int out_size) {
  const float* ts = (const float*)d_in[0];
  const float* y0 = (const float*)d_in[1];
  const float* W0 = (const float*)d_in[2];
  const float* b0 = (const float*)d_in[3];
  const float* W1 = (const float*)d_in[4];
  const float* b1 = (const float*)d_in[5];
  const float* W2 = (const float*)d_in[6];
  const float* b2 = (const float*)d_in[7];
  float* out = (float*)d_out;

  static int configured = 0;
  if (!configured) {
    cudaFuncSetAttribute(solve_kernel, cudaFuncAttributeMaxDynamicSharedMemorySize, NSTG * STG);
    configured = 1;
  }

  init_kernel<<<(TT * NELEM) / NTHR, NTHR>>>(ts, y0, W0, W1, W2, out);
  solve_kernel<<<NBLK, NTHR, NSTG * STG>>>(ts, b0, b1, b2, out);
}